// round 7
// baseline (speedup 1.0000x reference)
#include <cuda_runtime.h>
#include <cuda_bf16.h>
#include <cstdint>

// Shapes (fixed for this problem)
//   x:        [16, 512, 64, 64] f32
//   w:        [16, 512]         f32
//   weight:   [512, 512, 3, 3]  f32
//   affine_w: [512, 512]        f32
//   affine_b: [512]             f32
//   out:      [16, 512, 64, 64] f32
#define NB   16
#define NC   512
#define NH   64
#define NW   64
#define NHW  4096

// -------- device scratch (no allocations allowed) --------
__device__ float g_s [NB * NC];          // modulation scale s[b,i]
__device__ float g_w2[NC * NC];          // W2[o,i] = sum_{kh,kw} weight^2
__device__ float g_d [NB * NC];          // demod d[b,o]
__device__ float g_wt[9 * NC * NC];      // Wt[pos][ci][co], tf32-rounded

__device__ __forceinline__ uint32_t f2tf32(float f) {
    uint32_t r;
    asm("cvt.rna.tf32.f32 %0, %1;" : "=r"(r) : "f"(f));
    return r;
}

__device__ __forceinline__ void mma_tf32(float* c, const uint32_t* a, const uint32_t* b) {
    asm volatile(
        "mma.sync.aligned.m16n8k8.row.col.f32.tf32.tf32.f32 "
        "{%0,%1,%2,%3}, {%4,%5,%6,%7}, {%8,%9}, {%0,%1,%2,%3};"
        : "+f"(c[0]), "+f"(c[1]), "+f"(c[2]), "+f"(c[3])
        : "r"(a[0]), "r"(a[1]), "r"(a[2]), "r"(a[3]),
          "r"(b[0]), "r"(b[1]));
}

// -------- prep kernels --------

// s[b,i] = dot(w[b,:], affine_w[i,:]) + affine_b[i] + 1
// one warp per (b,i); grid (64,16), block 256
__global__ void k_modscale(const float* __restrict__ w,
                           const float* __restrict__ aw,
                           const float* __restrict__ ab) {
    int b    = blockIdx.y;
    int warp = threadIdx.x >> 5;
    int lane = threadIdx.x & 31;
    int i    = blockIdx.x * 8 + warp;
    const float* wrow = w  + b * NC;
    const float* arow = aw + i * NC;
    float sum = 0.f;
#pragma unroll
    for (int j = lane; j < NC; j += 32) sum += wrow[j] * arow[j];
#pragma unroll
    for (int off = 16; off; off >>= 1) sum += __shfl_xor_sync(0xffffffffu, sum, off);
    if (lane == 0) g_s[b * NC + i] = sum + ab[i] + 1.0f;
}

// W2[o*512+i] = sum_{t<9} weight[(o*512+i)*9+t]^2 ; one thread per (o,i)
__global__ void k_w2(const float* __restrict__ weight) {
    int idx = blockIdx.x * blockDim.x + threadIdx.x;   // < 262144
    const float* p = weight + idx * 9;
    float s = 0.f;
#pragma unroll
    for (int t = 0; t < 9; t++) s += p[t] * p[t];
    g_w2[idx] = s;
}

// Wt[pos][ci][co] = tf32(weight[co][ci][pos]) ; coalesced write
__global__ void k_wt(const float* __restrict__ weight) {
    int idx = blockIdx.x * blockDim.x + threadIdx.x;   // < 9*512*512
    int co  = idx & 511;
    int ci  = (idx >> 9) & 511;
    int pos = idx >> 18;
    float v = weight[(co * NC + ci) * 9 + pos];
    g_wt[idx] = __uint_as_float(f2tf32(v));
}

// d[b,o] = rsqrt( sum_i s[b,i]^2 * W2[o,i] + 1e-8 ) ; one warp per (b,o)
__global__ void k_demod() {
    int b    = blockIdx.y;
    int warp = threadIdx.x >> 5;
    int lane = threadIdx.x & 31;
    int o    = blockIdx.x * 8 + warp;
    const float* srow = g_s  + b * NC;
    const float* w2r  = g_w2 + o * NC;
    float sum = 0.f;
#pragma unroll
    for (int j = lane; j < NC; j += 32) {
        float sv = srow[j];
        sum += sv * sv * w2r[j];
    }
#pragma unroll
    for (int off = 16; off; off >>= 1) sum += __shfl_xor_sync(0xffffffffu, sum, off);
    if (lane == 0) g_d[b * NC + o] = rsqrtf(sum + 1e-8f);
}

// -------- main conv: implicit GEMM, tf32 mma.sync --------
// Block: 256 thr (8 warps, 2x4).  Tile: BM=128 c_out, BN=128 px (2 rows), BK=32.
// O[b, co, px] = d[b,co] * sum_{pos, ci} Wt[pos][ci][co] * (s[b,ci] * x[b,ci,shift(px,pos)])
#define PITCH 132

__global__ void __launch_bounds__(256, 2)
k_conv(const float* __restrict__ x, float* __restrict__ out) {
    __shared__ float As[32 * PITCH];   // [k][m]
    __shared__ float Bs[32 * PITCH];   // [k][n]
    __shared__ float sS[NC];

    const int tid     = threadIdx.x;
    const int b       = blockIdx.z;
    const int row0    = blockIdx.y * 2;       // two image rows per tile
    const int co_base = blockIdx.x * 128;
    const int warp    = tid >> 5;
    const int lane    = tid & 31;
    const int wm      = warp >> 2;            // 0..1 (64 rows each)
    const int wn      = warp & 3;             // 0..3 (32 cols each)
    const int g       = lane >> 2;            // groupID 0..7
    const int t       = lane & 3;             // thread-in-group 0..3

    sS[tid]       = g_s[b * NC + tid];
    sS[tid + 256] = g_s[b * NC + tid + 256];
    __syncthreads();

    const float* xb = x + b * (NC * NHW);

    float acc[4][4][4];
#pragma unroll
    for (int im = 0; im < 4; im++)
#pragma unroll
        for (int in = 0; in < 4; in++)
#pragma unroll
            for (int q = 0; q < 4; q++) acc[im][in][q] = 0.f;

    for (int pos = 0; pos < 9; ++pos) {
        const int kh = pos / 3 - 1;           // -1..1
        const int kw = pos - (pos / 3) * 3 - 1;
        const float* wtp = g_wt + pos * (NC * NC) + co_base;

        for (int c0 = 0; c0 < NC; c0 += 32) {
            // ---- stage A tile: Wt[pos][c0+k][co_base+m] (coalesced) ----
#pragma unroll
            for (int j = 0; j < 16; j++) {
                int idx = tid + 256 * j;
                int k = idx >> 7, m = idx & 127;
                As[k * PITCH + m] = wtp[(c0 + k) * NC + m];
            }
            // ---- stage B tile: tf32( x[b, c0+k, r, c] * s[b, c0+k] ), padded ----
#pragma unroll
            for (int j = 0; j < 16; j++) {
                int idx = tid + 256 * j;
                int k = idx >> 7, n = idx & 127;
                int r = row0 + (n >> 6) + kh;
                int c = (n & 63) + kw;
                float v = 0.f;
                if ((unsigned)r < (unsigned)NH && (unsigned)c < (unsigned)NW)
                    v = xb[((c0 + k) << 12) + (r << 6) + c] * sS[c0 + k];
                Bs[k * PITCH + n] = __uint_as_float(f2tf32(v));
            }
            __syncthreads();

            // ---- 4 k-steps of 8, 16 mma each ----
#pragma unroll
            for (int ks = 0; ks < 4; ++ks) {
                const int krow = ks * 8 + t;
                uint32_t af[4][4];
                uint32_t bf[4][2];
#pragma unroll
                for (int im = 0; im < 4; im++) {
                    const float* p = &As[krow * PITCH + wm * 64 + im * 16 + g];
                    af[im][0] = __float_as_uint(p[0]);
                    af[im][1] = __float_as_uint(p[8]);
                    af[im][2] = __float_as_uint(p[4 * PITCH]);
                    af[im][3] = __float_as_uint(p[4 * PITCH + 8]);
                }
#pragma unroll
                for (int in = 0; in < 4; in++) {
                    const float* p = &Bs[krow * PITCH + wn * 32 + in * 8 + g];
                    bf[in][0] = __float_as_uint(p[0]);
                    bf[in][1] = __float_as_uint(p[4 * PITCH]);
                }
#pragma unroll
                for (int im = 0; im < 4; im++)
#pragma unroll
                    for (int in = 0; in < 4; in++)
                        mma_tf32(acc[im][in], af[im], bf[in]);
            }
            __syncthreads();
        }
    }

    // ---- epilogue: scale by d[b,co], store float2 ----
    float* ob = out + (b * NC + co_base) * NHW + row0 * NW;
#pragma unroll
    for (int im = 0; im < 4; im++) {
        int m0 = wm * 64 + im * 16 + g;
        float d0 = g_d[b * NC + co_base + m0];
        float d1 = g_d[b * NC + co_base + m0 + 8];
#pragma unroll
        for (int in = 0; in < 4; in++) {
            int n = wn * 32 + in * 8 + t * 2;
            float2 v0 = make_float2(acc[im][in][0] * d0, acc[im][in][1] * d0);
            float2 v1 = make_float2(acc[im][in][2] * d1, acc[im][in][3] * d1);
            *(float2*)(ob + m0 * NHW + n)       = v0;
            *(float2*)(ob + (m0 + 8) * NHW + n) = v1;
        }
    }
}

// -------- launch --------
extern "C" void kernel_launch(void* const* d_in, const int* in_sizes, int n_in,
                              void* d_out, int out_size) {
    (void)in_sizes; (void)n_in; (void)out_size;
    const float* x      = (const float*)d_in[0];
    const float* w      = (const float*)d_in[1];
    const float* weight = (const float*)d_in[2];
    const float* aw     = (const float*)d_in[3];
    const float* ab     = (const float*)d_in[4];
    float* out = (float*)d_out;

    k_modscale<<<dim3(64, 16), 256>>>(w, aw, ab);
    k_w2<<<1024, 256>>>(weight);          // 262144 / 256
    k_wt<<<9216, 256>>>(weight);          // 2359296 / 256
    k_demod<<<dim3(64, 16), 256>>>();
    k_conv<<<dim3(4, 32, 16), 256>>>(x, out);
}

// round 8
// speedup vs baseline: 1.0004x; 1.0004x over previous
#include <cuda_runtime.h>
#include <cuda_bf16.h>
#include <cstdint>

// Shapes (fixed for this problem)
//   x:        [16, 512, 64, 64] f32
//   w:        [16, 512]         f32
//   weight:   [512, 512, 3, 3]  f32
//   affine_w: [512, 512]        f32
//   affine_b: [512]             f32
//   out:      [16, 512, 64, 64] f32
#define NB   16
#define NC   512
#define NH   64
#define NW   64
#define NHW  4096

// -------- device scratch (no allocations allowed) --------
__device__ float g_s [NB * NC];          // modulation scale s[b,i]
__device__ float g_w2[NC * NC];          // W2[o,i] = sum_{kh,kw} weight^2
__device__ float g_d [NB * NC];          // demod d[b,o]
__device__ float g_wt[9 * NC * NC];      // Wt[pos][ci][co], tf32-rounded

__device__ __forceinline__ uint32_t f2tf32(float f) {
    uint32_t r;
    asm("cvt.rna.tf32.f32 %0, %1;" : "=r"(r) : "f"(f));
    return r;
}

__device__ __forceinline__ void mma_tf32(float* c, const uint32_t* a, const uint32_t* b) {
    asm volatile(
        "mma.sync.aligned.m16n8k8.row.col.f32.tf32.tf32.f32 "
        "{%0,%1,%2,%3}, {%4,%5,%6,%7}, {%8,%9}, {%0,%1,%2,%3};"
        : "+f"(c[0]), "+f"(c[1]), "+f"(c[2]), "+f"(c[3])
        : "r"(a[0]), "r"(a[1]), "r"(a[2]), "r"(a[3]),
          "r"(b[0]), "r"(b[1]));
}

// -------- prep kernels --------

// s[b,i] = dot(w[b,:], affine_w[i,:]) + affine_b[i] + 1
// one warp per (b,i); grid (64,16), block 256
__global__ void k_modscale(const float* __restrict__ w,
                           const float* __restrict__ aw,
                           const float* __restrict__ ab) {
    int b    = blockIdx.y;
    int warp = threadIdx.x >> 5;
    int lane = threadIdx.x & 31;
    int i    = blockIdx.x * 8 + warp;
    const float* wrow = w  + b * NC;
    const float* arow = aw + i * NC;
    float sum = 0.f;
#pragma unroll
    for (int j = lane; j < NC; j += 32) sum += wrow[j] * arow[j];
#pragma unroll
    for (int off = 16; off; off >>= 1) sum += __shfl_xor_sync(0xffffffffu, sum, off);
    if (lane == 0) g_s[b * NC + i] = sum + ab[i] + 1.0f;
}

// W2[o*512+i] = sum_{t<9} weight[(o*512+i)*9+t]^2 ; one thread per (o,i)
__global__ void k_w2(const float* __restrict__ weight) {
    int idx = blockIdx.x * blockDim.x + threadIdx.x;   // < 262144
    const float* p = weight + idx * 9;
    float s = 0.f;
#pragma unroll
    for (int t = 0; t < 9; t++) s += p[t] * p[t];
    g_w2[idx] = s;
}

// Wt[pos][ci][co] = tf32(weight[co][ci][pos]) ; coalesced write
__global__ void k_wt(const float* __restrict__ weight) {
    int idx = blockIdx.x * blockDim.x + threadIdx.x;   // < 9*512*512
    int co  = idx & 511;
    int ci  = (idx >> 9) & 511;
    int pos = idx >> 18;
    float v = weight[(co * NC + ci) * 9 + pos];
    g_wt[idx] = __uint_as_float(f2tf32(v));
}

// d[b,o] = rsqrt( sum_i s[b,i]^2 * W2[o,i] + 1e-8 ) ; one warp per (b,o)
__global__ void k_demod() {
    int b    = blockIdx.y;
    int warp = threadIdx.x >> 5;
    int lane = threadIdx.x & 31;
    int o    = blockIdx.x * 8 + warp;
    const float* srow = g_s  + b * NC;
    const float* w2r  = g_w2 + o * NC;
    float sum = 0.f;
#pragma unroll
    for (int j = lane; j < NC; j += 32) {
        float sv = srow[j];
        sum += sv * sv * w2r[j];
    }
#pragma unroll
    for (int off = 16; off; off >>= 1) sum += __shfl_xor_sync(0xffffffffu, sum, off);
    if (lane == 0) g_d[b * NC + o] = rsqrtf(sum + 1e-8f);
}

// -------- main conv: implicit GEMM, tf32 mma.sync --------
// Block: 256 thr (8 warps, 2x4).  Tile: BM=128 c_out, BN=128 px (2 rows), BK=32.
// O[b, co, px] = d[b,co] * sum_{pos, ci} Wt[pos][ci][co] * (s[b,ci] * x[b,ci,shift(px,pos)])
#define PITCH 132

__global__ void __launch_bounds__(256, 2)
k_conv(const float* __restrict__ x, float* __restrict__ out) {
    __shared__ float As[32 * PITCH];   // [k][m]
    __shared__ float Bs[32 * PITCH];   // [k][n]
    __shared__ float sS[NC];

    const int tid     = threadIdx.x;
    const int b       = blockIdx.z;
    const int row0    = blockIdx.y * 2;       // two image rows per tile
    const int co_base = blockIdx.x * 128;
    const int warp    = tid >> 5;
    const int lane    = tid & 31;
    const int wm      = warp >> 2;            // 0..1 (64 rows each)
    const int wn      = warp & 3;             // 0..3 (32 cols each)
    const int g       = lane >> 2;            // groupID 0..7
    const int t       = lane & 3;             // thread-in-group 0..3

    sS[tid]       = g_s[b * NC + tid];
    sS[tid + 256] = g_s[b * NC + tid + 256];
    __syncthreads();

    const float* xb = x + b * (NC * NHW);

    float acc[4][4][4];
#pragma unroll
    for (int im = 0; im < 4; im++)
#pragma unroll
        for (int in = 0; in < 4; in++)
#pragma unroll
            for (int q = 0; q < 4; q++) acc[im][in][q] = 0.f;

    for (int pos = 0; pos < 9; ++pos) {
        const int kh = pos / 3 - 1;           // -1..1
        const int kw = pos - (pos / 3) * 3 - 1;
        const float* wtp = g_wt + pos * (NC * NC) + co_base;

        for (int c0 = 0; c0 < NC; c0 += 32) {
            // ---- stage A tile: Wt[pos][c0+k][co_base+m] (coalesced) ----
#pragma unroll
            for (int j = 0; j < 16; j++) {
                int idx = tid + 256 * j;
                int k = idx >> 7, m = idx & 127;
                As[k * PITCH + m] = wtp[(c0 + k) * NC + m];
            }
            // ---- stage B tile: tf32( x[b, c0+k, r, c] * s[b, c0+k] ), padded ----
#pragma unroll
            for (int j = 0; j < 16; j++) {
                int idx = tid + 256 * j;
                int k = idx >> 7, n = idx & 127;
                int r = row0 + (n >> 6) + kh;
                int c = (n & 63) + kw;
                float v = 0.f;
                if ((unsigned)r < (unsigned)NH && (unsigned)c < (unsigned)NW)
                    v = xb[((c0 + k) << 12) + (r << 6) + c] * sS[c0 + k];
                Bs[k * PITCH + n] = __uint_as_float(f2tf32(v));
            }
            __syncthreads();

            // ---- 4 k-steps of 8, 16 mma each ----
#pragma unroll
            for (int ks = 0; ks < 4; ++ks) {
                const int krow = ks * 8 + t;
                uint32_t af[4][4];
                uint32_t bf[4][2];
#pragma unroll
                for (int im = 0; im < 4; im++) {
                    const float* p = &As[krow * PITCH + wm * 64 + im * 16 + g];
                    af[im][0] = __float_as_uint(p[0]);
                    af[im][1] = __float_as_uint(p[8]);
                    af[im][2] = __float_as_uint(p[4 * PITCH]);
                    af[im][3] = __float_as_uint(p[4 * PITCH + 8]);
                }
#pragma unroll
                for (int in = 0; in < 4; in++) {
                    const float* p = &Bs[krow * PITCH + wn * 32 + in * 8 + g];
                    bf[in][0] = __float_as_uint(p[0]);
                    bf[in][1] = __float_as_uint(p[4 * PITCH]);
                }
#pragma unroll
                for (int im = 0; im < 4; im++)
#pragma unroll
                    for (int in = 0; in < 4; in++)
                        mma_tf32(acc[im][in], af[im], bf[in]);
            }
            __syncthreads();
        }
    }

    // ---- epilogue: scale by d[b,co], store float2 ----
    float* ob = out + (b * NC + co_base) * NHW + row0 * NW;
#pragma unroll
    for (int im = 0; im < 4; im++) {
        int m0 = wm * 64 + im * 16 + g;
        float d0 = g_d[b * NC + co_base + m0];
        float d1 = g_d[b * NC + co_base + m0 + 8];
#pragma unroll
        for (int in = 0; in < 4; in++) {
            int n = wn * 32 + in * 8 + t * 2;
            float2 v0 = make_float2(acc[im][in][0] * d0, acc[im][in][1] * d0);
            float2 v1 = make_float2(acc[im][in][2] * d1, acc[im][in][3] * d1);
            *(float2*)(ob + m0 * NHW + n)       = v0;
            *(float2*)(ob + (m0 + 8) * NHW + n) = v1;
        }
    }
}

// -------- launch --------
extern "C" void kernel_launch(void* const* d_in, const int* in_sizes, int n_in,
                              void* d_out, int out_size) {
    (void)in_sizes; (void)n_in; (void)out_size;
    const float* x      = (const float*)d_in[0];
    const float* w      = (const float*)d_in[1];
    const float* weight = (const float*)d_in[2];
    const float* aw     = (const float*)d_in[3];
    const float* ab     = (const float*)d_in[4];
    float* out = (float*)d_out;

    k_modscale<<<dim3(64, 16), 256>>>(w, aw, ab);
    k_w2<<<1024, 256>>>(weight);          // 262144 / 256
    k_wt<<<9216, 256>>>(weight);          // 2359296 / 256
    k_demod<<<dim3(64, 16), 256>>>();
    k_conv<<<dim3(4, 32, 16), 256>>>(x, out);
}

// round 9
// speedup vs baseline: 1.3165x; 1.3160x over previous
#include <cuda_runtime.h>
#include <cuda_bf16.h>
#include <cstdint>

// Shapes (fixed for this problem)
//   x:        [16, 512, 64, 64] f32
//   w:        [16, 512]         f32
//   weight:   [512, 512, 3, 3]  f32
//   affine_w: [512, 512]        f32
//   affine_b: [512]             f32
//   out:      [16, 512, 64, 64] f32
#define NB   16
#define NC   512
#define NH   64
#define NW   64
#define NHW  4096

// -------- device scratch (no allocations allowed) --------
__device__ float g_s [NB * NC];          // modulation scale s[b,i]
__device__ float g_w2[NC * NC];          // W2[o,i] = sum_{kh,kw} weight^2
__device__ float g_d [NB * NC];          // demod d[b,o]
__device__ float g_wt[9 * NC * NC];      // Wt[pos][ci][co], tf32-rounded

__device__ __forceinline__ uint32_t f2tf32(float f) {
    uint32_t r;
    asm("cvt.rna.tf32.f32 %0, %1;" : "=r"(r) : "f"(f));
    return r;
}

__device__ __forceinline__ void mma_tf32(float* c, const uint32_t* a, const uint32_t* b) {
    asm volatile(
        "mma.sync.aligned.m16n8k8.row.col.f32.tf32.tf32.f32 "
        "{%0,%1,%2,%3}, {%4,%5,%6,%7}, {%8,%9}, {%0,%1,%2,%3};"
        : "+f"(c[0]), "+f"(c[1]), "+f"(c[2]), "+f"(c[3])
        : "r"(a[0]), "r"(a[1]), "r"(a[2]), "r"(a[3]),
          "r"(b[0]), "r"(b[1]));
}

// -------- prep kernels --------

__global__ void k_modscale(const float* __restrict__ w,
                           const float* __restrict__ aw,
                           const float* __restrict__ ab) {
    int b    = blockIdx.y;
    int warp = threadIdx.x >> 5;
    int lane = threadIdx.x & 31;
    int i    = blockIdx.x * 8 + warp;
    const float* wrow = w  + b * NC;
    const float* arow = aw + i * NC;
    float sum = 0.f;
#pragma unroll
    for (int j = lane; j < NC; j += 32) sum += wrow[j] * arow[j];
#pragma unroll
    for (int off = 16; off; off >>= 1) sum += __shfl_xor_sync(0xffffffffu, sum, off);
    if (lane == 0) g_s[b * NC + i] = sum + ab[i] + 1.0f;
}

__global__ void k_w2(const float* __restrict__ weight) {
    int idx = blockIdx.x * blockDim.x + threadIdx.x;   // < 262144
    const float* p = weight + idx * 9;
    float s = 0.f;
#pragma unroll
    for (int t = 0; t < 9; t++) s += p[t] * p[t];
    g_w2[idx] = s;
}

__global__ void k_wt(const float* __restrict__ weight) {
    int idx = blockIdx.x * blockDim.x + threadIdx.x;   // < 9*512*512
    int co  = idx & 511;
    int ci  = (idx >> 9) & 511;
    int pos = idx >> 18;
    float v = weight[(co * NC + ci) * 9 + pos];
    g_wt[idx] = __uint_as_float(f2tf32(v));
}

__global__ void k_demod() {
    int b    = blockIdx.y;
    int warp = threadIdx.x >> 5;
    int lane = threadIdx.x & 31;
    int o    = blockIdx.x * 8 + warp;
    const float* srow = g_s  + b * NC;
    const float* w2r  = g_w2 + o * NC;
    float sum = 0.f;
#pragma unroll
    for (int j = lane; j < NC; j += 32) {
        float sv = srow[j];
        sum += sv * sv * w2r[j];
    }
#pragma unroll
    for (int off = 16; off; off >>= 1) sum += __shfl_xor_sync(0xffffffffu, sum, off);
    if (lane == 0) g_d[b * NC + o] = rsqrtf(sum + 1e-8f);
}

// -------- main conv: implicit GEMM, tf32 mma.sync, x-halo reuse + cp.async --------
// Block: 256 thr (8 warps, 2x4).  Tile: BM=128 c_out, BN=128 px (2 rows), BK=32 c_in.
// Per ci-chunk: stage halo tile of tf32(x*s) once; reuse for all 9 filter positions.
// A tiles (pre-tf32 weights) streamed gmem->smem via cp.async, double-buffered.

#define APITCH 132                   // A k-row pitch (floats); banks 4t+g: conflict-free
#define ASZ    (32 * APITCH)         // 4224 floats per A buffer
#define BKS    292                   // B k-stride (292 % 32 == 4): conflict-free frags
#define BRS    68                    // B row stride (4 halo rows of 66 used cols)
#define BSZ    (32 * BKS)            // 9344 floats
#define SMEM_FLOATS (2 * ASZ + BSZ + NC)
#define SMEM_BYTES  (SMEM_FLOATS * 4)

__device__ __forceinline__ void prefetch_A(const float* __restrict__ wtp,
                                           float* dstbuf, int tid) {
#pragma unroll
    for (int j = 0; j < 4; j++) {
        int idx = tid + 256 * j;           // 0..1023
        int k   = idx >> 5;                // 0..31
        int c16 = idx & 31;                // 16B chunk within 512B k-row
        const float* src = wtp + k * NC + c16 * 4;
        uint32_t dst = (uint32_t)__cvta_generic_to_shared(dstbuf + k * APITCH + c16 * 4);
        asm volatile("cp.async.cg.shared.global [%0], [%1], 16;" :: "r"(dst), "l"(src));
    }
    asm volatile("cp.async.commit_group;" ::: "memory");
}

__global__ void __launch_bounds__(256, 2)
k_conv(const float* __restrict__ x, float* __restrict__ out) {
    extern __shared__ float smem[];
    float* As = smem;                       // [2][32][APITCH]
    float* Bs = smem + 2 * ASZ;             // [32][4][BRS] (k-stride BKS)
    float* sS = smem + 2 * ASZ + BSZ;       // [512]

    const int tid     = threadIdx.x;
    const int b       = blockIdx.z;
    const int row0    = blockIdx.y * 2;     // two output rows per tile
    const int co_base = blockIdx.x * 128;
    const int warp    = tid >> 5;
    const int lane    = tid & 31;
    const int wm      = warp >> 2;          // 0..1
    const int wn      = warp & 3;           // 0..3
    const int g       = lane >> 2;          // 0..7
    const int t       = lane & 3;           // 0..3

    // kick off first A prefetch immediately (chunk 0, pos 0 -> buf 0)
    prefetch_A(g_wt + co_base, As, tid);

    sS[tid]       = g_s[b * NC + tid];
    sS[tid + 256] = g_s[b * NC + tid + 256];

    const float* xb = x + b * (NC * NHW);

    // per-thread B fragment n-offsets (n = wn*32 + in*8 + g)
    int noff[4];
#pragma unroll
    for (int in = 0; in < 4; in++) {
        int n = wn * 32 + in * 8 + g;
        noff[in] = (n >> 6) * BRS + (n & 63);
    }

    float acc[4][4][4];
#pragma unroll
    for (int im = 0; im < 4; im++)
#pragma unroll
        for (int in = 0; in < 4; in++)
#pragma unroll
            for (int q = 0; q < 4; q++) acc[im][in][q] = 0.f;

    __syncthreads();   // sS visible; also fences before first B staging

    int cur = 0;
    for (int c0 = 0; c0 < NC; c0 += 32) {
        // ---- stage B halo tile once per ci chunk:  Bs[k][r][c] = tf32(x*s) ----
        // logical idx over 32*272 = 8704 = 34*256 exactly
#pragma unroll
        for (int j = 0; j < 34; j++) {
            int idx = tid + 256 * j;
            int k   = idx / 272;
            int rem = idx - k * 272;
            int r   = rem / BRS;            // 0..3  (image row row0-1+r)
            int c   = rem - r * BRS;        // 0..67 (image col c-1)
            int xr  = row0 - 1 + r;
            int xc  = c - 1;
            float v = 0.f;
            if ((unsigned)xr < (unsigned)NH && (unsigned)xc < (unsigned)NW)
                v = xb[((c0 + k) << 12) + (xr << 6) + xc] * sS[c0 + k];
            Bs[k * BKS + r * BRS + c] = __uint_as_float(f2tf32(v));
        }

#pragma unroll 1
        for (int pos = 0; pos < 9; pos++) {
            // prefetch next A tile into the other buffer
            int npos = pos + 1, nc0 = c0;
            if (npos == 9) { npos = 0; nc0 = c0 + 32; if (nc0 == NC) nc0 = 0; }
            prefetch_A(g_wt + npos * (NC * NC) + nc0 * NC + co_base,
                       As + (cur ^ 1) * ASZ, tid);

            // wait current A tile (oldest of the 2 in-flight groups)
            asm volatile("cp.async.wait_group 1;" ::: "memory");
            __syncthreads();   // A visible to all; B staged (pos 0)

            const int  kh = pos / 3 - 1;
            const int  kw = pos - (pos / 3) * 3 - 1;
            const float* Ab = As + cur * ASZ;
            const float* Bb = Bs + (1 + kh) * BRS + (1 + kw);

#pragma unroll
            for (int ks = 0; ks < 4; ++ks) {
                const int krow = ks * 8 + t;
                uint32_t af[4][4];
                uint32_t bf[4][2];
#pragma unroll
                for (int im = 0; im < 4; im++) {
                    const float* p = Ab + krow * APITCH + wm * 64 + im * 16 + g;
                    af[im][0] = __float_as_uint(p[0]);
                    af[im][1] = __float_as_uint(p[8]);
                    af[im][2] = __float_as_uint(p[4 * APITCH]);
                    af[im][3] = __float_as_uint(p[4 * APITCH + 8]);
                }
#pragma unroll
                for (int in = 0; in < 4; in++) {
                    const float* p = Bb + krow * BKS + noff[in];
                    bf[in][0] = __float_as_uint(p[0]);
                    bf[in][1] = __float_as_uint(p[4 * BKS]);
                }
#pragma unroll
                for (int im = 0; im < 4; im++)
#pragma unroll
                    for (int in = 0; in < 4; in++)
                        mma_tf32(acc[im][in], af[im], bf[in]);
            }
            __syncthreads();   // all warps done with As[cur] (and Bs at chunk end)
            cur ^= 1;
        }
    }

    // ---- epilogue: scale by d[b,co], store float2 ----
    float* ob = out + (b * NC + co_base) * NHW + row0 * NW;
#pragma unroll
    for (int im = 0; im < 4; im++) {
        int m0 = wm * 64 + im * 16 + g;
        float d0 = g_d[b * NC + co_base + m0];
        float d1 = g_d[b * NC + co_base + m0 + 8];
#pragma unroll
        for (int in = 0; in < 4; in++) {
            int n = wn * 32 + in * 8 + t * 2;
            float2 v0 = make_float2(acc[im][in][0] * d0, acc[im][in][1] * d0);
            float2 v1 = make_float2(acc[im][in][2] * d1, acc[im][in][3] * d1);
            *(float2*)(ob + m0 * NHW + n)       = v0;
            *(float2*)(ob + (m0 + 8) * NHW + n) = v1;
        }
    }
}

// -------- launch --------
extern "C" void kernel_launch(void* const* d_in, const int* in_sizes, int n_in,
                              void* d_out, int out_size) {
    (void)in_sizes; (void)n_in; (void)out_size;
    const float* x      = (const float*)d_in[0];
    const float* w      = (const float*)d_in[1];
    const float* weight = (const float*)d_in[2];
    const float* aw     = (const float*)d_in[3];
    const float* ab     = (const float*)d_in[4];
    float* out = (float*)d_out;

    static bool attr_set = false;
    if (!attr_set) {
        cudaFuncSetAttribute(k_conv, cudaFuncAttributeMaxDynamicSharedMemorySize,
                             SMEM_BYTES);
        attr_set = true;
    }

    k_modscale<<<dim3(64, 16), 256>>>(w, aw, ab);
    k_w2<<<1024, 256>>>(weight);
    k_wt<<<9216, 256>>>(weight);
    k_demod<<<dim3(64, 16), 256>>>();
    k_conv<<<dim3(4, 32, 16), 256, SMEM_BYTES>>>(x, out);
}